// round 2
// baseline (speedup 1.0000x reference)
#include <cuda_runtime.h>
#include <cstdint>
#include <cstddef>

// ---------------- problem constants ----------------
#define EMB   768
#define HDIM  64
#define NHEAD 12
#define NB    16
#define NH    56
#define NW    56
#define NTOK  (NB*NH*NW)          // 50176
#define SCALING 0.125f            // 64^-0.5

// ---------------- scratch (device globals; allocation-free) ----------------
// g_q: Q, later overwritten by height-attention output
// g_k: K (pre-scaled)
// g_v: V, later overwritten by width-attention output (vw)
__device__ float g_q[(size_t)NTOK * EMB];
__device__ float g_k[(size_t)NTOK * EMB];
__device__ float g_v[(size_t)NTOK * EMB];

// ---------------- tf32 helpers ----------------
__device__ __forceinline__ unsigned f2tf(float x) {
    unsigned r;
    asm("cvt.rna.tf32.f32 %0, %1;" : "=r"(r) : "f"(x));
    return r;
}

__device__ __forceinline__ void mma_tf32(float* d, const unsigned* a, const unsigned* b) {
    asm volatile(
        "mma.sync.aligned.m16n8k8.row.col.f32.tf32.tf32.f32 "
        "{%0,%1,%2,%3}, {%4,%5,%6,%7}, {%8,%9}, {%0,%1,%2,%3};\n"
        : "+f"(d[0]), "+f"(d[1]), "+f"(d[2]), "+f"(d[3])
        : "r"(a[0]), "r"(a[1]), "r"(a[2]), "r"(a[3]),
          "r"(b[0]), "r"(b[1]));
}

// ---------------- GEMM: C[M,768] = (A[M,768] @ W[768,768]^T + bias) * scale ----
// y[m][n] = sum_k A[m][k] * W[n][k]   (both K-major -> mma row.col)
// Tiles: BM=128, BN=128, BK=16; 256 threads (8 warps: 4 along M x 2 along N),
// warp tile 32x64 = 2x8 m16n8k8 mma tiles. Double-buffered smem, tf32 operands.
#define BM 128
#define BN 128
#define BK 16
#define SLD 132   // padded leading dim for transposed smem tiles [k][m]

__global__ __launch_bounds__(256)
void gemm_tf32(const float* __restrict__ A, const float* __restrict__ W,
               const float* __restrict__ bias, float* __restrict__ C,
               float scale)
{
    __shared__ unsigned As[2][BK][SLD];   // As[buf][k][m]
    __shared__ unsigned Bs[2][BK][SLD];   // Bs[buf][k][n]

    const int tid = threadIdx.x;
    const int m0 = blockIdx.x * BM;
    const int n0 = blockIdx.y * BN;

    // loader mapping: 256 threads -> (kGroup 0..3) x (row 0..63), rows +0 and +64
    const int lkG = tid & 3;
    const int lm  = tid >> 2;

    // compute mapping
    const int warp = tid >> 5, lane = tid & 31;
    const int g = lane >> 2, tig = lane & 3;
    const int wm = (warp & 3) * 32;       // warp M offset in tile
    const int wn = (warp >> 2) * 64;      // warp N offset in tile

    const float* Aptr0 = A + (size_t)(m0 + lm)      * EMB + lkG * 4;
    const float* Aptr1 = A + (size_t)(m0 + lm + 64) * EMB + lkG * 4;
    const float* Bptr0 = W + (size_t)(n0 + lm)      * EMB + lkG * 4;
    const float* Bptr1 = W + (size_t)(n0 + lm + 64) * EMB + lkG * 4;

    float acc[2][8][4];
    #pragma unroll
    for (int i = 0; i < 2; ++i)
        #pragma unroll
        for (int j = 0; j < 8; ++j)
            #pragma unroll
            for (int l = 0; l < 4; ++l) acc[i][j][l] = 0.f;

    // ---- preload tile 0 ----
    {
        float av0[4], av1[4], bv0[4], bv1[4];
        *(float4*)av0 = *(const float4*)(Aptr0);
        *(float4*)av1 = *(const float4*)(Aptr1);
        *(float4*)bv0 = *(const float4*)(Bptr0);
        *(float4*)bv1 = *(const float4*)(Bptr1);
        #pragma unroll
        for (int j = 0; j < 4; ++j) {
            As[0][lkG*4 + j][lm]      = f2tf(av0[j]);
            As[0][lkG*4 + j][lm + 64] = f2tf(av1[j]);
            Bs[0][lkG*4 + j][lm]      = f2tf(bv0[j]);
            Bs[0][lkG*4 + j][lm + 64] = f2tf(bv1[j]);
        }
    }
    __syncthreads();

    const int NK = EMB / BK;   // 48
    for (int t = 0; t < NK; ++t) {
        const int cur = t & 1;
        float av0[4], av1[4], bv0[4], bv1[4];
        const bool havenext = (t + 1 < NK);
        if (havenext) {
            const int k0 = (t + 1) * BK;
            *(float4*)av0 = *(const float4*)(Aptr0 + k0);
            *(float4*)av1 = *(const float4*)(Aptr1 + k0);
            *(float4*)bv0 = *(const float4*)(Bptr0 + k0);
            *(float4*)bv1 = *(const float4*)(Bptr1 + k0);
        }

        // compute on current buffer: two k8 steps
        #pragma unroll
        for (int kk = 0; kk < BK; kk += 8) {
            unsigned af[2][4];
            unsigned bf[8][2];
            #pragma unroll
            for (int mt = 0; mt < 2; ++mt) {
                const int r = wm + mt * 16 + g;
                af[mt][0] = As[cur][kk + tig    ][r];
                af[mt][1] = As[cur][kk + tig    ][r + 8];
                af[mt][2] = As[cur][kk + tig + 4][r];
                af[mt][3] = As[cur][kk + tig + 4][r + 8];
            }
            #pragma unroll
            for (int nt = 0; nt < 8; ++nt) {
                const int c = wn + nt * 8 + g;
                bf[nt][0] = Bs[cur][kk + tig    ][c];
                bf[nt][1] = Bs[cur][kk + tig + 4][c];
            }
            #pragma unroll
            for (int mt = 0; mt < 2; ++mt)
                #pragma unroll
                for (int nt = 0; nt < 8; ++nt)
                    mma_tf32(acc[mt][nt], af[mt], bf[nt]);
        }

        if (havenext) {
            const int nxt = cur ^ 1;
            #pragma unroll
            for (int j = 0; j < 4; ++j) {
                As[nxt][lkG*4 + j][lm]      = f2tf(av0[j]);
                As[nxt][lkG*4 + j][lm + 64] = f2tf(av1[j]);
                Bs[nxt][lkG*4 + j][lm]      = f2tf(bv0[j]);
                Bs[nxt][lkG*4 + j][lm + 64] = f2tf(bv1[j]);
            }
        }
        __syncthreads();
    }

    // ---- epilogue: C = (acc + bias) * scale ----
    #pragma unroll
    for (int mt = 0; mt < 2; ++mt) {
        const int rbase = m0 + wm + mt * 16 + g;
        #pragma unroll
        for (int nt = 0; nt < 8; ++nt) {
            const int cbase = n0 + wn + nt * 8 + tig * 2;
            const float b0v = bias[cbase];
            const float b1v = bias[cbase + 1];
            C[(size_t)rbase * EMB + cbase]           = (acc[mt][nt][0] + b0v) * scale;
            C[(size_t)rbase * EMB + cbase + 1]       = (acc[mt][nt][1] + b1v) * scale;
            C[(size_t)(rbase + 8) * EMB + cbase]     = (acc[mt][nt][2] + b0v) * scale;
            C[(size_t)(rbase + 8) * EMB + cbase + 1] = (acc[mt][nt][3] + b1v) * scale;
        }
    }
}

// ---------------- axial attention ----------------
// One CTA per (batch, outer, head). axis=0 (width): rows are the W positions of
// a fixed (b, y) -> row stride EMB. axis=1 (height): rows are the H positions of
// a fixed (b, w) -> row stride NW*EMB. Q,K,V rows (56 x 64) staged in smem,
// S=Q K^T softmaxed per row, O = S V written back with identical indexing.
// K is pre-scaled by SCALING in its GEMM epilogue.
__global__ __launch_bounds__(256)
void attn_kernel(const float* __restrict__ q, const float* __restrict__ k,
                 const float* __restrict__ v, float* __restrict__ o, int axis)
{
    __shared__ float Qs[NH * HDIM];     // 56 x 64
    __shared__ float Kt[HDIM * 65];     // transposed, padded: Kt[d][y]
    __shared__ float Vs[NH * HDIM];     // 56 x 64
    __shared__ float Pr[8 * 64];        // per-warp softmax row

    const int bid = blockIdx.x;
    const int n = bid % NHEAD;
    const int rem = bid / NHEAD;
    const int outer = rem % NH;
    const int b = rem / NH;

    size_t base;
    long stride;
    if (axis == 0) {                                     // width attention
        base = ((size_t)(b * NH + outer) * NW) * EMB + (size_t)n * HDIM;
        stride = EMB;
    } else {                                             // height attention
        base = ((size_t)b * NH * NW + outer) * EMB + (size_t)n * HDIM;
        stride = (long)NW * EMB;
    }

    const int tid = threadIdx.x;
    for (int i = tid; i < NH * HDIM; i += 256) {
        const int r = i >> 6, d = i & 63;
        const size_t gaddr = base + (size_t)r * stride + d;
        Qs[i]          = q[gaddr];
        Kt[d * 65 + r] = k[gaddr];
        Vs[i]          = v[gaddr];
    }
    __syncthreads();

    const int warp = tid >> 5, lane = tid & 31;
    const bool hi = (lane < NH - 32);   // lane+32 is a valid key index (<56)
    float* prow = &Pr[warp * 64];

    for (int x = warp; x < NH; x += 8) {
        const float* qrow = &Qs[x * HDIM];
        float s0 = 0.f, s1 = 0.f;
        #pragma unroll
        for (int d = 0; d < HDIM; ++d) {
            const float qv = qrow[d];
            s0 += qv * Kt[d * 65 + lane];
            s1 += qv * Kt[d * 65 + lane + 32];  // cols 56..63 are junk, masked below
        }

        float m = fmaxf(s0, hi ? s1 : -1e30f);
        #pragma unroll
        for (int off = 16; off; off >>= 1)
            m = fmaxf(m, __shfl_xor_sync(0xffffffffu, m, off));
        const float e0 = __expf(s0 - m);
        const float e1 = hi ? __expf(s1 - m) : 0.f;
        float sum = e0 + e1;
        #pragma unroll
        for (int off = 16; off; off >>= 1)
            sum += __shfl_xor_sync(0xffffffffu, sum, off);
        const float inv = __fdividef(1.f, sum);

        prow[lane]      = e0 * inv;
        prow[lane + 32] = e1 * inv;
        __syncwarp();

        float o0 = 0.f, o1 = 0.f;
        #pragma unroll 8
        for (int y = 0; y < NH; ++y) {
            const float p = prow[y];
            o0 += p * Vs[y * HDIM + lane];
            o1 += p * Vs[y * HDIM + lane + 32];
        }
        const size_t oaddr = base + (size_t)x * stride;
        o[oaddr + lane]      = o0;
        o[oaddr + lane + 32] = o1;
        __syncwarp();   // all lanes done reading Pr before next x overwrites it
    }
}

// ---------------- launch ----------------
extern "C" void kernel_launch(void* const* d_in, const int* in_sizes, int n_in,
                              void* d_out, int out_size)
{
    (void)in_sizes; (void)n_in; (void)out_size;
    const float* x  = (const float*)d_in[0];
    const float* Wq = (const float*)d_in[1];
    const float* bq = (const float*)d_in[2];
    const float* Wk = (const float*)d_in[3];
    const float* bk = (const float*)d_in[4];
    const float* Wv = (const float*)d_in[5];
    const float* bv = (const float*)d_in[6];
    const float* Wo = (const float*)d_in[7];
    const float* bo = (const float*)d_in[8];
    float* out = (float*)d_out;

    float *qp, *kp, *vp;
    cudaGetSymbolAddress((void**)&qp, g_q);
    cudaGetSymbolAddress((void**)&kp, g_k);
    cudaGetSymbolAddress((void**)&vp, g_v);

    const dim3 grid(NTOK / BM, EMB / BN);   // 392 x 6
    const dim3 blk(256);

    // QKV projections (K pre-scaled by 1/sqrt(d))
    gemm_tf32<<<grid, blk>>>(x, Wq, bq, qp, 1.0f);
    gemm_tf32<<<grid, blk>>>(x, Wk, bk, kp, SCALING);
    gemm_tf32<<<grid, blk>>>(x, Wv, bv, vp, 1.0f);

    // width attention: vw overwrites V (per-CTA slices staged in smem first)
    attn_kernel<<<NB * NH * NHEAD, blk>>>(qp, kp, vp, vp, 0);
    // height attention over vw: output overwrites Q
    attn_kernel<<<NB * NW * NHEAD, blk>>>(qp, kp, vp, qp, 1);

    // output projection
    gemm_tf32<<<grid, blk>>>(qp, Wo, bo, out, 1.0f);
}

// round 8
// speedup vs baseline: 1.2119x; 1.2119x over previous
#include <cuda_runtime.h>
#include <cstdint>
#include <cstddef>

// ---------------- problem constants ----------------
#define EMB   768
#define HDIM  64
#define NHEAD 12
#define NB    16
#define NH    56
#define NW    56
#define NTOK  (NB*NH*NW)          // 50176
#define SCALING 0.125f            // 64^-0.5

// ---------------- scratch (device globals; allocation-free) ----------------
__device__ float g_q[(size_t)NTOK * EMB];
__device__ float g_k[(size_t)NTOK * EMB];
__device__ float g_v[(size_t)NTOK * EMB];

// ---------------- tf32 helpers ----------------
__device__ __forceinline__ unsigned f2tf(float x) {
    unsigned r;
    asm("cvt.rna.tf32.f32 %0, %1;" : "=r"(r) : "f"(x));
    return r;
}

__device__ __forceinline__ void mma_tf32(float* d, const unsigned* a, const unsigned* b) {
    asm volatile(
        "mma.sync.aligned.m16n8k8.row.col.f32.tf32.tf32.f32 "
        "{%0,%1,%2,%3}, {%4,%5,%6,%7}, {%8,%9}, {%0,%1,%2,%3};\n"
        : "+f"(d[0]), "+f"(d[1]), "+f"(d[2]), "+f"(d[3])
        : "r"(a[0]), "r"(a[1]), "r"(a[2]), "r"(a[3]),
          "r"(b[0]), "r"(b[1]));
}

// ---------------- GEMM: C[M,768] = (A[M,768] @ W[768,768]^T + bias) * scale ----
#define BM 128
#define BN 128
#define BK 16
#define SLD 132

__global__ __launch_bounds__(256)
void gemm_tf32(const float* __restrict__ A, const float* __restrict__ W,
               const float* __restrict__ bias, float* __restrict__ C,
               float scale)
{
    __shared__ unsigned As[2][BK][SLD];   // As[buf][k][m]
    __shared__ unsigned Bs[2][BK][SLD];   // Bs[buf][k][n]

    const int tid = threadIdx.x;
    const int m0 = blockIdx.x * BM;
    const int n0 = blockIdx.y * BN;

    const int lkG = tid & 3;
    const int lm  = tid >> 2;

    const int warp = tid >> 5, lane = tid & 31;
    const int g = lane >> 2, tig = lane & 3;
    const int wm = (warp & 3) * 32;
    const int wn = (warp >> 2) * 64;

    const float* Aptr0 = A + (size_t)(m0 + lm)      * EMB + lkG * 4;
    const float* Aptr1 = A + (size_t)(m0 + lm + 64) * EMB + lkG * 4;
    const float* Bptr0 = W + (size_t)(n0 + lm)      * EMB + lkG * 4;
    const float* Bptr1 = W + (size_t)(n0 + lm + 64) * EMB + lkG * 4;

    float acc[2][8][4];
    #pragma unroll
    for (int i = 0; i < 2; ++i)
        #pragma unroll
        for (int j = 0; j < 8; ++j)
            #pragma unroll
            for (int l = 0; l < 4; ++l) acc[i][j][l] = 0.f;

    {
        float av0[4], av1[4], bv0[4], bv1[4];
        *(float4*)av0 = *(const float4*)(Aptr0);
        *(float4*)av1 = *(const float4*)(Aptr1);
        *(float4*)bv0 = *(const float4*)(Bptr0);
        *(float4*)bv1 = *(const float4*)(Bptr1);
        #pragma unroll
        for (int j = 0; j < 4; ++j) {
            As[0][lkG*4 + j][lm]      = f2tf(av0[j]);
            As[0][lkG*4 + j][lm + 64] = f2tf(av1[j]);
            Bs[0][lkG*4 + j][lm]      = f2tf(bv0[j]);
            Bs[0][lkG*4 + j][lm + 64] = f2tf(bv1[j]);
        }
    }
    __syncthreads();

    const int NK = EMB / BK;   // 48
    for (int t = 0; t < NK; ++t) {
        const int cur = t & 1;
        float av0[4], av1[4], bv0[4], bv1[4];
        const bool havenext = (t + 1 < NK);
        if (havenext) {
            const int k0 = (t + 1) * BK;
            *(float4*)av0 = *(const float4*)(Aptr0 + k0);
            *(float4*)av1 = *(const float4*)(Aptr1 + k0);
            *(float4*)bv0 = *(const float4*)(Bptr0 + k0);
            *(float4*)bv1 = *(const float4*)(Bptr1 + k0);
        }

        #pragma unroll
        for (int kk = 0; kk < BK; kk += 8) {
            unsigned af[2][4];
            unsigned bf[8][2];
            #pragma unroll
            for (int mt = 0; mt < 2; ++mt) {
                const int r = wm + mt * 16 + g;
                af[mt][0] = As[cur][kk + tig    ][r];
                af[mt][1] = As[cur][kk + tig    ][r + 8];
                af[mt][2] = As[cur][kk + tig + 4][r];
                af[mt][3] = As[cur][kk + tig + 4][r + 8];
            }
            #pragma unroll
            for (int nt = 0; nt < 8; ++nt) {
                const int c = wn + nt * 8 + g;
                bf[nt][0] = Bs[cur][kk + tig    ][c];
                bf[nt][1] = Bs[cur][kk + tig + 4][c];
            }
            #pragma unroll
            for (int mt = 0; mt < 2; ++mt)
                #pragma unroll
                for (int nt = 0; nt < 8; ++nt)
                    mma_tf32(acc[mt][nt], af[mt], bf[nt]);
        }

        if (havenext) {
            const int nxt = cur ^ 1;
            #pragma unroll
            for (int j = 0; j < 4; ++j) {
                As[nxt][lkG*4 + j][lm]      = f2tf(av0[j]);
                As[nxt][lkG*4 + j][lm + 64] = f2tf(av1[j]);
                Bs[nxt][lkG*4 + j][lm]      = f2tf(bv0[j]);
                Bs[nxt][lkG*4 + j][lm + 64] = f2tf(bv1[j]);
            }
        }
        __syncthreads();
    }

    #pragma unroll
    for (int mt = 0; mt < 2; ++mt) {
        const int rbase = m0 + wm + mt * 16 + g;
        #pragma unroll
        for (int nt = 0; nt < 8; ++nt) {
            const int cbase = n0 + wn + nt * 8 + tig * 2;
            const float b0v = bias[cbase];
            const float b1v = bias[cbase + 1];
            C[(size_t)rbase * EMB + cbase]           = (acc[mt][nt][0] + b0v) * scale;
            C[(size_t)rbase * EMB + cbase + 1]       = (acc[mt][nt][1] + b1v) * scale;
            C[(size_t)(rbase + 8) * EMB + cbase]     = (acc[mt][nt][2] + b0v) * scale;
            C[(size_t)(rbase + 8) * EMB + cbase + 1] = (acc[mt][nt][3] + b1v) * scale;
        }
    }
}

// ---------------- tensor-core axial attention ----------------
// One CTA per (batch, outer, head). 56 rows padded to 64.
// smem (dynamic, tf32 as u32, ld=68):
//   QT [d=64][68]  : Q^T (A operand of S = Q K^T)   -> reused as P^T [y][x] after softmax
//   KT [d=64][68]  : K^T (B operand)                -> reused as S float [x][y]
//   VS [y=64][68]  : V row-major (B operand of O = P V)
#define ALD 68
#define ATT_SMEM (3 * 64 * ALD * 4)

__global__ __launch_bounds__(256)
void attn_tc(const float* __restrict__ q, const float* __restrict__ k,
             const float* __restrict__ v, float* __restrict__ o, int axis)
{
    extern __shared__ unsigned sm[];
    unsigned* QT = sm;                 // also P^T
    unsigned* KT = sm + 64 * ALD;      // also S (float)
    unsigned* VS = sm + 2 * 64 * ALD;
    float* Sf = (float*)KT;

    const int bid = blockIdx.x;
    const int n = bid % NHEAD;
    const int rem = bid / NHEAD;
    const int outer = rem % NH;
    const int b = rem / NH;

    size_t base;
    long stride;
    if (axis == 0) {                                     // width attention
        base = ((size_t)(b * NH + outer) * NW) * EMB + (size_t)n * HDIM;
        stride = EMB;
    } else {                                             // height attention
        base = ((size_t)b * NH * NW + outer) * EMB + (size_t)n * HDIM;
        stride = (long)NW * EMB;
    }

    const int tid = threadIdx.x;
    for (int i = tid; i < NH * HDIM; i += 256) {
        const int r = i >> 6, d = i & 63;
        const size_t gaddr = base + (size_t)r * stride + d;
        QT[d * ALD + r] = f2tf(q[gaddr]);
        KT[d * ALD + r] = f2tf(k[gaddr]);
        VS[r * ALD + d] = f2tf(v[gaddr]);
    }
    __syncthreads();

    const int warp = tid >> 5, lane = tid & 31;
    const int g8 = lane >> 2, tig = lane & 3;
    const int wm = (warp & 3) * 16;     // 4 m-tiles of 16
    const int wn = (warp >> 2) * 32;    // 2 n-halves of 32

    // ---- S = Q K^T  (M=64, N=64, K=64) ----
    float acc[4][4];
    #pragma unroll
    for (int nt = 0; nt < 4; ++nt)
        #pragma unroll
        for (int l = 0; l < 4; ++l) acc[nt][l] = 0.f;

    #pragma unroll
    for (int kk = 0; kk < 64; kk += 8) {
        unsigned af[4];
        af[0] = QT[(kk + tig    ) * ALD + wm + g8];
        af[1] = QT[(kk + tig    ) * ALD + wm + g8 + 8];
        af[2] = QT[(kk + tig + 4) * ALD + wm + g8];
        af[3] = QT[(kk + tig + 4) * ALD + wm + g8 + 8];
        #pragma unroll
        for (int nt = 0; nt < 4; ++nt) {
            unsigned bf[2];
            bf[0] = KT[(kk + tig    ) * ALD + wn + nt * 8 + g8];
            bf[1] = KT[(kk + tig + 4) * ALD + wn + nt * 8 + g8];
            mma_tf32(acc[nt], af, bf);
        }
    }
    __syncthreads();   // all QT/KT reads complete before overwriting KT with S

    #pragma unroll
    for (int nt = 0; nt < 4; ++nt) {
        const int c = wn + nt * 8 + tig * 2;
        Sf[(wm + g8    ) * ALD + c]     = acc[nt][0];
        Sf[(wm + g8    ) * ALD + c + 1] = acc[nt][1];
        Sf[(wm + g8 + 8) * ALD + c]     = acc[nt][2];
        Sf[(wm + g8 + 8) * ALD + c + 1] = acc[nt][3];
    }
    __syncthreads();

    // ---- softmax rows, write P^T (tf32) into QT region ----
    // warp w handles rows w, w+8, ..., w+48 (7 rows, all < 56)
    for (int x = warp; x < NH; x += 8) {
        const float s0 = Sf[x * ALD + lane];
        const bool hi = (lane < NH - 32);
        const float s1 = hi ? Sf[x * ALD + lane + 32] : -1e30f;
        float m = fmaxf(s0, s1);
        #pragma unroll
        for (int off = 16; off; off >>= 1)
            m = fmaxf(m, __shfl_xor_sync(0xffffffffu, m, off));
        const float e0 = __expf(s0 - m);
        const float e1 = hi ? __expf(s1 - m) : 0.f;
        float sum = e0 + e1;
        #pragma unroll
        for (int off = 16; off; off >>= 1)
            sum += __shfl_xor_sync(0xffffffffu, sum, off);
        const float inv = __fdividef(1.f, sum);

        QT[lane * ALD + x] = f2tf(e0 * inv);
        if (hi) QT[(lane + 32) * ALD + x] = f2tf(e1 * inv);
    }
    __syncthreads();

    // ---- O = P V  (M=64, N=64, K=56 -> exactly 7 k8 steps, no pad reads) ----
    float oc[4][4];
    #pragma unroll
    for (int nt = 0; nt < 4; ++nt)
        #pragma unroll
        for (int l = 0; l < 4; ++l) oc[nt][l] = 0.f;

    #pragma unroll
    for (int kk = 0; kk < NH; kk += 8) {
        unsigned af[4];
        af[0] = QT[(kk + tig    ) * ALD + wm + g8];
        af[1] = QT[(kk + tig    ) * ALD + wm + g8 + 8];
        af[2] = QT[(kk + tig + 4) * ALD + wm + g8];
        af[3] = QT[(kk + tig + 4) * ALD + wm + g8 + 8];
        #pragma unroll
        for (int nt = 0; nt < 4; ++nt) {
            unsigned bf[2];
            bf[0] = VS[(kk + tig    ) * ALD + wn + nt * 8 + g8];
            bf[1] = VS[(kk + tig + 4) * ALD + wn + nt * 8 + g8];
            mma_tf32(oc[nt], af, bf);
        }
    }

    const int r0 = wm + g8, r1 = wm + g8 + 8;
    #pragma unroll
    for (int nt = 0; nt < 4; ++nt) {
        const int c = wn + nt * 8 + tig * 2;
        if (r0 < NH) {
            o[base + (size_t)r0 * stride + c]     = oc[nt][0];
            o[base + (size_t)r0 * stride + c + 1] = oc[nt][1];
        }
        if (r1 < NH) {
            o[base + (size_t)r1 * stride + c]     = oc[nt][2];
            o[base + (size_t)r1 * stride + c + 1] = oc[nt][3];
        }
    }
}

// ---------------- launch ----------------
extern "C" void kernel_launch(void* const* d_in, const int* in_sizes, int n_in,
                              void* d_out, int out_size)
{
    (void)in_sizes; (void)n_in; (void)out_size;
    const float* x  = (const float*)d_in[0];
    const float* Wq = (const float*)d_in[1];
    const float* bq = (const float*)d_in[2];
    const float* Wk = (const float*)d_in[3];
    const float* bk = (const float*)d_in[4];
    const float* Wv = (const float*)d_in[5];
    const float* bv = (const float*)d_in[6];
    const float* Wo = (const float*)d_in[7];
    const float* bo = (const float*)d_in[8];
    float* out = (float*)d_out;

    float *qp, *kp, *vp;
    cudaGetSymbolAddress((void**)&qp, g_q);
    cudaGetSymbolAddress((void**)&kp, g_k);
    cudaGetSymbolAddress((void**)&vp, g_v);

    cudaFuncSetAttribute(attn_tc, cudaFuncAttributeMaxDynamicSharedMemorySize, ATT_SMEM);

    const dim3 grid(NTOK / BM, EMB / BN);   // 392 x 6
    const dim3 blk(256);

    // QKV projections (K pre-scaled by 1/sqrt(d))
    gemm_tf32<<<grid, blk>>>(x, Wq, bq, qp, 1.0f);
    gemm_tf32<<<grid, blk>>>(x, Wk, bk, kp, SCALING);
    gemm_tf32<<<grid, blk>>>(x, Wv, bv, vp, 1.0f);

    // width attention: vw overwrites V (per-CTA slices staged in smem first)
    attn_tc<<<NB * NH * NHEAD, blk, ATT_SMEM>>>(qp, kp, vp, vp, 0);
    // height attention over vw: output overwrites Q
    attn_tc<<<NB * NW * NHEAD, blk, ATT_SMEM>>>(qp, kp, vp, qp, 1);

    // output projection
    gemm_tf32<<<grid, blk>>>(qp, Wo, bo, out, 1.0f);
}

// round 10
// speedup vs baseline: 1.3146x; 1.0847x over previous
#include <cuda_runtime.h>
#include <cstdint>
#include <cstddef>

// ---------------- problem constants ----------------
#define EMB   768
#define HDIM  64
#define NHEAD 12
#define NB    16
#define NH    56
#define NW    56
#define NTOK  (NB*NH*NW)          // 50176
#define SCALING 0.125f            // 64^-0.5

// ---------------- scratch (device globals; allocation-free) ----------------
__device__ float g_q[(size_t)NTOK * EMB];
__device__ float g_k[(size_t)NTOK * EMB];
__device__ float g_v[(size_t)NTOK * EMB];

// ---------------- tf32 helpers ----------------
__device__ __forceinline__ unsigned f2tf(float x) {
    unsigned r;
    asm("cvt.rna.tf32.f32 %0, %1;" : "=r"(r) : "f"(x));
    return r;
}

__device__ __forceinline__ void mma_tf32(float* d, const unsigned* a, const unsigned* b) {
    asm volatile(
        "mma.sync.aligned.m16n8k8.row.col.f32.tf32.tf32.f32 "
        "{%0,%1,%2,%3}, {%4,%5,%6,%7}, {%8,%9}, {%0,%1,%2,%3};\n"
        : "+f"(d[0]), "+f"(d[1]), "+f"(d[2]), "+f"(d[3])
        : "r"(a[0]), "r"(a[1]), "r"(a[2]), "r"(a[3]),
          "r"(b[0]), "r"(b[1]));
}

// ---------------- GEMM v2: C[M,768] = (A[M,768] @ W[768,768]^T + bias)*scale --
// Tile: BM=128, BN=256, BK=16. 8 warps as 2(M) x 4(N); warp tile 64x64
// (mt=4 x nt=8 m16n8k8 tiles) -> 32 LDS.32 per 32 mma per k8 step.
// smem leading dims 136/264 (== 8 mod 32): fragment LDS fully conflict-free.
// grid: (nsel*3, 392); x%3 -> n-tile, x/3 -> weight select (QKV fusion shares
// A tiles through L2 because sel/ntile vary fastest within a wave).
#define BM2 128
#define BN2 256
#define BK2 16
#define LDA2 136
#define LDB2 264
#define AS_U32 (2*BK2*LDA2)
#define BS_U32 (2*BK2*LDB2)
#define GEMM_SMEM ((AS_U32 + BS_U32) * 4)   // 51200 bytes

__global__ __launch_bounds__(256)
void gemm_tf32b(const float* __restrict__ A,
                const float* __restrict__ W0, const float* __restrict__ W1,
                const float* __restrict__ W2,
                const float* __restrict__ b0, const float* __restrict__ b1,
                const float* __restrict__ b2,
                float* __restrict__ C0, float* __restrict__ C1, float* __restrict__ C2,
                float s0, float s1, float s2)
{
    extern __shared__ unsigned usm[];
    unsigned* As = usm;            // [2][BK2][LDA2]
    unsigned* Bs = usm + AS_U32;   // [2][BK2][LDB2]

    const int sel = blockIdx.x / 3;
    const int n0  = (blockIdx.x % 3) * BN2;
    const int m0  = blockIdx.y * BM2;
    const float* W    = (sel == 0) ? W0 : (sel == 1) ? W1 : W2;
    const float* bias = (sel == 0) ? b0 : (sel == 1) ? b1 : b2;
    float* C          = (sel == 0) ? C0 : (sel == 1) ? C1 : C2;
    const float scale = (sel == 0) ? s0 : (sel == 1) ? s1 : s2;

    const int tid = threadIdx.x;
    const int lkG = tid & 3;           // k-group (4 floats)
    const int lm  = tid >> 2;          // 0..63

    const int warp = tid >> 5, lane = tid & 31;
    const int g = lane >> 2, tig = lane & 3;
    const int wm = (warp & 1) * 64;    // warp M offset
    const int wn = (warp >> 1) * 64;   // warp N offset

    const float* Ap0 = A + (size_t)(m0 + lm)       * EMB + lkG * 4;
    const float* Ap1 = A + (size_t)(m0 + lm + 64)  * EMB + lkG * 4;
    const float* Bp0 = W + (size_t)(n0 + lm)       * EMB + lkG * 4;
    const float* Bp1 = W + (size_t)(n0 + lm + 64)  * EMB + lkG * 4;
    const float* Bp2 = W + (size_t)(n0 + lm + 128) * EMB + lkG * 4;
    const float* Bp3 = W + (size_t)(n0 + lm + 192) * EMB + lkG * 4;

    float acc[4][8][4];
    #pragma unroll
    for (int mt = 0; mt < 4; ++mt)
        #pragma unroll
        for (int nt = 0; nt < 8; ++nt)
            #pragma unroll
            for (int l = 0; l < 4; ++l) acc[mt][nt][l] = 0.f;

    // ---- preload chunk 0 ----
    {
        float4 a0 = *(const float4*)(Ap0);
        float4 a1 = *(const float4*)(Ap1);
        float4 v0 = *(const float4*)(Bp0);
        float4 v1 = *(const float4*)(Bp1);
        float4 v2 = *(const float4*)(Bp2);
        float4 v3 = *(const float4*)(Bp3);
        const float* aa0 = (const float*)&a0; const float* aa1 = (const float*)&a1;
        const float* bb0 = (const float*)&v0; const float* bb1 = (const float*)&v1;
        const float* bb2 = (const float*)&v2; const float* bb3 = (const float*)&v3;
        #pragma unroll
        for (int j = 0; j < 4; ++j) {
            const int kk = lkG * 4 + j;
            As[kk * LDA2 + lm]       = f2tf(aa0[j]);
            As[kk * LDA2 + lm + 64]  = f2tf(aa1[j]);
            Bs[kk * LDB2 + lm]       = f2tf(bb0[j]);
            Bs[kk * LDB2 + lm + 64]  = f2tf(bb1[j]);
            Bs[kk * LDB2 + lm + 128] = f2tf(bb2[j]);
            Bs[kk * LDB2 + lm + 192] = f2tf(bb3[j]);
        }
    }
    __syncthreads();

    const int NKC = EMB / BK2;   // 48
    for (int t = 0; t < NKC; ++t) {
        const int cur = t & 1;
        const unsigned* Ac = As + cur * (BK2 * LDA2);
        const unsigned* Bc = Bs + cur * (BK2 * LDB2);

        float4 a0, a1, v0, v1, v2, v3;
        const bool havenext = (t + 1 < NKC);
        if (havenext) {
            const int k0 = (t + 1) * BK2;
            a0 = *(const float4*)(Ap0 + k0);
            a1 = *(const float4*)(Ap1 + k0);
            v0 = *(const float4*)(Bp0 + k0);
            v1 = *(const float4*)(Bp1 + k0);
            v2 = *(const float4*)(Bp2 + k0);
            v3 = *(const float4*)(Bp3 + k0);
        }

        #pragma unroll
        for (int kk = 0; kk < BK2; kk += 8) {
            unsigned af[4][4];
            unsigned bf[8][2];
            #pragma unroll
            for (int mt = 0; mt < 4; ++mt) {
                const int r = wm + mt * 16 + g;
                af[mt][0] = Ac[(kk + tig    ) * LDA2 + r];
                af[mt][1] = Ac[(kk + tig    ) * LDA2 + r + 8];
                af[mt][2] = Ac[(kk + tig + 4) * LDA2 + r];
                af[mt][3] = Ac[(kk + tig + 4) * LDA2 + r + 8];
            }
            #pragma unroll
            for (int nt = 0; nt < 8; ++nt) {
                const int c = wn + nt * 8 + g;
                bf[nt][0] = Bc[(kk + tig    ) * LDB2 + c];
                bf[nt][1] = Bc[(kk + tig + 4) * LDB2 + c];
            }
            #pragma unroll
            for (int mt = 0; mt < 4; ++mt)
                #pragma unroll
                for (int nt = 0; nt < 8; ++nt)
                    mma_tf32(acc[mt][nt], af[mt], bf[nt]);
        }

        if (havenext) {
            const int nxt = cur ^ 1;
            unsigned* An = As + nxt * (BK2 * LDA2);
            unsigned* Bn = Bs + nxt * (BK2 * LDB2);
            const float* aa0 = (const float*)&a0; const float* aa1 = (const float*)&a1;
            const float* bb0 = (const float*)&v0; const float* bb1 = (const float*)&v1;
            const float* bb2 = (const float*)&v2; const float* bb3 = (const float*)&v3;
            #pragma unroll
            for (int j = 0; j < 4; ++j) {
                const int kk = lkG * 4 + j;
                An[kk * LDA2 + lm]       = f2tf(aa0[j]);
                An[kk * LDA2 + lm + 64]  = f2tf(aa1[j]);
                Bn[kk * LDB2 + lm]       = f2tf(bb0[j]);
                Bn[kk * LDB2 + lm + 64]  = f2tf(bb1[j]);
                Bn[kk * LDB2 + lm + 128] = f2tf(bb2[j]);
                Bn[kk * LDB2 + lm + 192] = f2tf(bb3[j]);
            }
        }
        __syncthreads();
    }

    // ---- epilogue: C = (acc + bias) * scale ----
    #pragma unroll
    for (int mt = 0; mt < 4; ++mt) {
        const int rbase = m0 + wm + mt * 16 + g;
        #pragma unroll
        for (int nt = 0; nt < 8; ++nt) {
            const int cbase = n0 + wn + nt * 8 + tig * 2;
            const float bv0 = bias[cbase];
            const float bv1 = bias[cbase + 1];
            C[(size_t)rbase * EMB + cbase]           = (acc[mt][nt][0] + bv0) * scale;
            C[(size_t)rbase * EMB + cbase + 1]       = (acc[mt][nt][1] + bv1) * scale;
            C[(size_t)(rbase + 8) * EMB + cbase]     = (acc[mt][nt][2] + bv0) * scale;
            C[(size_t)(rbase + 8) * EMB + cbase + 1] = (acc[mt][nt][3] + bv1) * scale;
        }
    }
}

// ---------------- tensor-core axial attention (unchanged from R8 pass) ----------------
#define ALD 68
#define ATT_SMEM (3 * 64 * ALD * 4)

__global__ __launch_bounds__(256)
void attn_tc(const float* __restrict__ q, const float* __restrict__ k,
             const float* __restrict__ v, float* __restrict__ o, int axis)
{
    extern __shared__ unsigned asm_[];
    unsigned* QT = asm_;                 // also P^T
    unsigned* KT = asm_ + 64 * ALD;      // also S (float)
    unsigned* VS = asm_ + 2 * 64 * ALD;
    float* Sf = (float*)KT;

    const int bid = blockIdx.x;
    const int n = bid % NHEAD;
    const int rem = bid / NHEAD;
    const int outer = rem % NH;
    const int b = rem / NH;

    size_t base;
    long stride;
    if (axis == 0) {
        base = ((size_t)(b * NH + outer) * NW) * EMB + (size_t)n * HDIM;
        stride = EMB;
    } else {
        base = ((size_t)b * NH * NW + outer) * EMB + (size_t)n * HDIM;
        stride = (long)NW * EMB;
    }

    const int tid = threadIdx.x;
    for (int i = tid; i < NH * HDIM; i += 256) {
        const int r = i >> 6, d = i & 63;
        const size_t gaddr = base + (size_t)r * stride + d;
        QT[d * ALD + r] = f2tf(q[gaddr]);
        KT[d * ALD + r] = f2tf(k[gaddr]);
        VS[r * ALD + d] = f2tf(v[gaddr]);
    }
    __syncthreads();

    const int warp = tid >> 5, lane = tid & 31;
    const int g8 = lane >> 2, tig = lane & 3;
    const int wm = (warp & 3) * 16;
    const int wn = (warp >> 2) * 32;

    float acc[4][4];
    #pragma unroll
    for (int nt = 0; nt < 4; ++nt)
        #pragma unroll
        for (int l = 0; l < 4; ++l) acc[nt][l] = 0.f;

    #pragma unroll
    for (int kk = 0; kk < 64; kk += 8) {
        unsigned af[4];
        af[0] = QT[(kk + tig    ) * ALD + wm + g8];
        af[1] = QT[(kk + tig    ) * ALD + wm + g8 + 8];
        af[2] = QT[(kk + tig + 4) * ALD + wm + g8];
        af[3] = QT[(kk + tig + 4) * ALD + wm + g8 + 8];
        #pragma unroll
        for (int nt = 0; nt < 4; ++nt) {
            unsigned bf[2];
            bf[0] = KT[(kk + tig    ) * ALD + wn + nt * 8 + g8];
            bf[1] = KT[(kk + tig + 4) * ALD + wn + nt * 8 + g8];
            mma_tf32(acc[nt], af, bf);
        }
    }
    __syncthreads();

    #pragma unroll
    for (int nt = 0; nt < 4; ++nt) {
        const int c = wn + nt * 8 + tig * 2;
        Sf[(wm + g8    ) * ALD + c]     = acc[nt][0];
        Sf[(wm + g8    ) * ALD + c + 1] = acc[nt][1];
        Sf[(wm + g8 + 8) * ALD + c]     = acc[nt][2];
        Sf[(wm + g8 + 8) * ALD + c + 1] = acc[nt][3];
    }
    __syncthreads();

    for (int x = warp; x < NH; x += 8) {
        const float s0 = Sf[x * ALD + lane];
        const bool hi = (lane < NH - 32);
        const float s1 = hi ? Sf[x * ALD + lane + 32] : -1e30f;
        float m = fmaxf(s0, s1);
        #pragma unroll
        for (int off = 16; off; off >>= 1)
            m = fmaxf(m, __shfl_xor_sync(0xffffffffu, m, off));
        const float e0 = __expf(s0 - m);
        const float e1 = hi ? __expf(s1 - m) : 0.f;
        float sum = e0 + e1;
        #pragma unroll
        for (int off = 16; off; off >>= 1)
            sum += __shfl_xor_sync(0xffffffffu, sum, off);
        const float inv = __fdividef(1.f, sum);

        QT[lane * ALD + x] = f2tf(e0 * inv);
        if (hi) QT[(lane + 32) * ALD + x] = f2tf(e1 * inv);
    }
    __syncthreads();

    float oc[4][4];
    #pragma unroll
    for (int nt = 0; nt < 4; ++nt)
        #pragma unroll
        for (int l = 0; l < 4; ++l) oc[nt][l] = 0.f;

    #pragma unroll
    for (int kk = 0; kk < NH; kk += 8) {
        unsigned af[4];
        af[0] = QT[(kk + tig    ) * ALD + wm + g8];
        af[1] = QT[(kk + tig    ) * ALD + wm + g8 + 8];
        af[2] = QT[(kk + tig + 4) * ALD + wm + g8];
        af[3] = QT[(kk + tig + 4) * ALD + wm + g8 + 8];
        #pragma unroll
        for (int nt = 0; nt < 4; ++nt) {
            unsigned bf[2];
            bf[0] = VS[(kk + tig    ) * ALD + wn + nt * 8 + g8];
            bf[1] = VS[(kk + tig + 4) * ALD + wn + nt * 8 + g8];
            mma_tf32(oc[nt], af, bf);
        }
    }

    const int r0 = wm + g8, r1 = wm + g8 + 8;
    #pragma unroll
    for (int nt = 0; nt < 4; ++nt) {
        const int c = wn + nt * 8 + tig * 2;
        if (r0 < NH) {
            o[base + (size_t)r0 * stride + c]     = oc[nt][0];
            o[base + (size_t)r0 * stride + c + 1] = oc[nt][1];
        }
        if (r1 < NH) {
            o[base + (size_t)r1 * stride + c]     = oc[nt][2];
            o[base + (size_t)r1 * stride + c + 1] = oc[nt][3];
        }
    }
}

// ---------------- launch ----------------
extern "C" void kernel_launch(void* const* d_in, const int* in_sizes, int n_in,
                              void* d_out, int out_size)
{
    (void)in_sizes; (void)n_in; (void)out_size;
    const float* x  = (const float*)d_in[0];
    const float* Wq = (const float*)d_in[1];
    const float* bq = (const float*)d_in[2];
    const float* Wk = (const float*)d_in[3];
    const float* bk = (const float*)d_in[4];
    const float* Wv = (const float*)d_in[5];
    const float* bv = (const float*)d_in[6];
    const float* Wo = (const float*)d_in[7];
    const float* bo = (const float*)d_in[8];
    float* out = (float*)d_out;

    float *qp, *kp, *vp;
    cudaGetSymbolAddress((void**)&qp, g_q);
    cudaGetSymbolAddress((void**)&kp, g_k);
    cudaGetSymbolAddress((void**)&vp, g_v);

    cudaFuncSetAttribute(gemm_tf32b, cudaFuncAttributeMaxDynamicSharedMemorySize, GEMM_SMEM);
    cudaFuncSetAttribute(attn_tc, cudaFuncAttributeMaxDynamicSharedMemorySize, ATT_SMEM);

    const dim3 blk(256);

    // fused QKV projections (K pre-scaled by 1/sqrt(d)); grid.x = 3 weights x 3 n-tiles
    gemm_tf32b<<<dim3(9, NTOK / BM2), blk, GEMM_SMEM>>>(
        x, Wq, Wk, Wv, bq, bk, bv, qp, kp, vp, 1.0f, SCALING, 1.0f);

    // width attention: vw overwrites V
    attn_tc<<<NB * NH * NHEAD, blk, ATT_SMEM>>>(qp, kp, vp, vp, 0);
    // height attention over vw: output overwrites Q
    attn_tc<<<NB * NW * NHEAD, blk, ATT_SMEM>>>(qp, kp, vp, qp, 1);

    // output projection
    gemm_tf32b<<<dim3(3, NTOK / BM2), blk, GEMM_SMEM>>>(
        qp, Wo, Wo, Wo, bo, bo, bo, out, out, out, 1.0f, 1.0f, 1.0f);
}

// round 13
// speedup vs baseline: 1.3788x; 1.0489x over previous
#include <cuda_runtime.h>
#include <cstdint>
#include <cstddef>

// ---------------- problem constants ----------------
#define EMB   768
#define HDIM  64
#define NHEAD 12
#define NB    16
#define NH    56
#define NW    56
#define NTOK  (NB*NH*NW)          // 50176
#define SCALING 0.125f            // 64^-0.5

// ---------------- scratch (device globals; allocation-free) ----------------
__device__ float g_q[(size_t)NTOK * EMB];
__device__ float g_k[(size_t)NTOK * EMB];
__device__ float g_v[(size_t)NTOK * EMB];

// ---------------- tf32 helpers ----------------
__device__ __forceinline__ unsigned f2tf(float x) {
    unsigned r;
    asm("cvt.rna.tf32.f32 %0, %1;" : "=r"(r) : "f"(x));
    return r;
}

__device__ __forceinline__ void mma_tf32(float* d, const unsigned* a, const unsigned* b) {
    asm volatile(
        "mma.sync.aligned.m16n8k8.row.col.f32.tf32.tf32.f32 "
        "{%0,%1,%2,%3}, {%4,%5,%6,%7}, {%8,%9}, {%0,%1,%2,%3};\n"
        : "+f"(d[0]), "+f"(d[1]), "+f"(d[2]), "+f"(d[3])
        : "r"(a[0]), "r"(a[1]), "r"(a[2]), "r"(a[3]),
          "r"(b[0]), "r"(b[1]));
}

// ---------------- GEMM v3 ----------------
// C[M,768] = (A[M,768] @ W[768,768]^T + bias) * scale.
// 512 threads = 16 warps as 4(M) x 4(N); warp tile 32x64 (mt=2 x nt=8).
// BM=128, BN=256, BK=16, double-buffered smem.
// XOR-swizzled smem layout: idx(k,m) = k*LD + (m ^ ((k&12)<<1)).
//   - STS conflict-free (lanes: m ^ 8*kG covers all 32 banks)
//   - fragment LDS conflict-free (swizzle term constant per instruction,
//     8*tig + g spans 32 banks since LD == 8 mod 32)
#define BM3 128
#define BN3 256
#define BK3 16
#define LDA3 136
#define LDB3 264
#define AIDX(k, m) ((k)*LDA3 + ((m) ^ (((k) & 12) << 1)))
#define BIDX(k, m) ((k)*LDB3 + ((m) ^ (((k) & 12) << 1)))
#define AS3_U32 (2*BK3*LDA3)
#define BS3_U32 (2*BK3*LDB3)
#define GEMM_SMEM ((AS3_U32 + BS3_U32) * 4)   // 51200 bytes

__global__ __launch_bounds__(512)
void gemm_tf32c(const float* __restrict__ A,
                const float* __restrict__ W0, const float* __restrict__ W1,
                const float* __restrict__ W2,
                const float* __restrict__ b0, const float* __restrict__ b1,
                const float* __restrict__ b2,
                float* __restrict__ C0, float* __restrict__ C1, float* __restrict__ C2,
                float s0, float s1, float s2)
{
    extern __shared__ unsigned usm[];
    unsigned* As = usm;             // [2][BK3][LDA3] swizzled
    unsigned* Bs = usm + AS3_U32;   // [2][BK3][LDB3] swizzled

    const int sel = blockIdx.x / 3;
    const int n0  = (blockIdx.x % 3) * BN3;
    const int m0  = blockIdx.y * BM3;
    const float* W    = (sel == 0) ? W0 : (sel == 1) ? W1 : W2;
    const float* bias = (sel == 0) ? b0 : (sel == 1) ? b1 : b2;
    float* C          = (sel == 0) ? C0 : (sel == 1) ? C1 : C2;
    const float scale = (sel == 0) ? s0 : (sel == 1) ? s1 : s2;

    const int tid = threadIdx.x;
    const int kg = tid & 3;            // k-group (4 floats)
    const int ra = tid >> 2;           // 0..127

    const int warp = tid >> 5, lane = tid & 31;
    const int g = lane >> 2, tig = lane & 3;
    const int wm = (warp & 3) * 32;    // warp M offset
    const int wn = (warp >> 2) * 64;   // warp N offset

    const float* Ap  = A + (size_t)(m0 + ra)       * EMB + kg * 4;
    const float* Bq0 = W + (size_t)(n0 + ra)       * EMB + kg * 4;
    const float* Bq1 = W + (size_t)(n0 + ra + 128) * EMB + kg * 4;

    float acc[2][8][4];
    #pragma unroll
    for (int mt = 0; mt < 2; ++mt)
        #pragma unroll
        for (int nt = 0; nt < 8; ++nt)
            #pragma unroll
            for (int l = 0; l < 4; ++l) acc[mt][nt][l] = 0.f;

    // ---- preload chunk 0 ----
    {
        float4 a0 = *(const float4*)(Ap);
        float4 v0 = *(const float4*)(Bq0);
        float4 v1 = *(const float4*)(Bq1);
        const float* aa = (const float*)&a0;
        const float* bb0 = (const float*)&v0;
        const float* bb1 = (const float*)&v1;
        #pragma unroll
        for (int j = 0; j < 4; ++j) {
            const int kk = kg * 4 + j;
            As[AIDX(kk, ra)]       = f2tf(aa[j]);
            Bs[BIDX(kk, ra)]       = f2tf(bb0[j]);
            Bs[BIDX(kk, ra + 128)] = f2tf(bb1[j]);
        }
    }
    __syncthreads();

    const int NKC = EMB / BK3;   // 48
    for (int t = 0; t < NKC; ++t) {
        const int cur = t & 1;
        const unsigned* Ac = As + cur * (BK3 * LDA3);
        const unsigned* Bc = Bs + cur * (BK3 * LDB3);

        float4 a0, v0, v1;
        const bool havenext = (t + 1 < NKC);
        if (havenext) {
            const int k0 = (t + 1) * BK3;
            a0 = *(const float4*)(Ap + k0);
            v0 = *(const float4*)(Bq0 + k0);
            v1 = *(const float4*)(Bq1 + k0);
        }

        #pragma unroll
        for (int kk = 0; kk < BK3; kk += 8) {
            unsigned af[2][4];
            unsigned bf[8][2];
            #pragma unroll
            for (int mt = 0; mt < 2; ++mt) {
                const int r = wm + mt * 16 + g;
                af[mt][0] = Ac[AIDX(kk + tig,     r)];
                af[mt][1] = Ac[AIDX(kk + tig,     r + 8)];
                af[mt][2] = Ac[AIDX(kk + tig + 4, r)];
                af[mt][3] = Ac[AIDX(kk + tig + 4, r + 8)];
            }
            #pragma unroll
            for (int nt = 0; nt < 8; ++nt) {
                const int c = wn + nt * 8 + g;
                bf[nt][0] = Bc[BIDX(kk + tig,     c)];
                bf[nt][1] = Bc[BIDX(kk + tig + 4, c)];
            }
            #pragma unroll
            for (int mt = 0; mt < 2; ++mt)
                #pragma unroll
                for (int nt = 0; nt < 8; ++nt)
                    mma_tf32(acc[mt][nt], af[mt], bf[nt]);
        }

        if (havenext) {
            const int nxt = cur ^ 1;
            unsigned* An = As + nxt * (BK3 * LDA3);
            unsigned* Bn = Bs + nxt * (BK3 * LDB3);
            const float* aa = (const float*)&a0;
            const float* bb0 = (const float*)&v0;
            const float* bb1 = (const float*)&v1;
            #pragma unroll
            for (int j = 0; j < 4; ++j) {
                const int kk = kg * 4 + j;
                An[AIDX(kk, ra)]       = f2tf(aa[j]);
                Bn[BIDX(kk, ra)]       = f2tf(bb0[j]);
                Bn[BIDX(kk, ra + 128)] = f2tf(bb1[j]);
            }
        }
        __syncthreads();
    }

    // ---- epilogue: C = (acc + bias) * scale ----
    #pragma unroll
    for (int mt = 0; mt < 2; ++mt) {
        const int rbase = m0 + wm + mt * 16 + g;
        #pragma unroll
        for (int nt = 0; nt < 8; ++nt) {
            const int cbase = n0 + wn + nt * 8 + tig * 2;
            const float bv0 = bias[cbase];
            const float bv1 = bias[cbase + 1];
            C[(size_t)rbase * EMB + cbase]           = (acc[mt][nt][0] + bv0) * scale;
            C[(size_t)rbase * EMB + cbase + 1]       = (acc[mt][nt][1] + bv1) * scale;
            C[(size_t)(rbase + 8) * EMB + cbase]     = (acc[mt][nt][2] + bv0) * scale;
            C[(size_t)(rbase + 8) * EMB + cbase + 1] = (acc[mt][nt][3] + bv1) * scale;
        }
    }
}

// ---------------- tensor-core axial attention ----------------
// ALD=72 (== 8 mod 32) + XOR swizzle on the two k-major tiles (QT/KT):
// fragment LDS fully conflict-free; VS row-major needs no swizzle (rows
// indexed by tig only); Sf overlay is row-major with stride-1 reads and
// conflict-free accumulator writes (8*g8 + 2*tig distinct).
#define ALD 72
#define QIDX(d, r) ((d)*ALD + ((r) ^ (((d) & 12) << 1)))
#define ATT_SMEM (3 * 64 * ALD * 4)   // 55296

__global__ __launch_bounds__(256)
void attn_tc(const float* __restrict__ q, const float* __restrict__ k,
             const float* __restrict__ v, float* __restrict__ o, int axis)
{
    extern __shared__ unsigned asm_[];
    unsigned* QT = asm_;                 // swizzled [d][r]; reused as P^T [y][x]
    unsigned* KT = asm_ + 64 * ALD;      // swizzled [d][r]; reused as S (plain float)
    unsigned* VS = asm_ + 2 * 64 * ALD;  // plain [y][d]
    float* Sf = (float*)KT;

    const int bid = blockIdx.x;
    const int n = bid % NHEAD;
    const int rem = bid / NHEAD;
    const int outer = rem % NH;
    const int b = rem / NH;

    size_t base;
    long stride;
    if (axis == 0) {
        base = ((size_t)(b * NH + outer) * NW) * EMB + (size_t)n * HDIM;
        stride = EMB;
    } else {
        base = ((size_t)b * NH * NW + outer) * EMB + (size_t)n * HDIM;
        stride = (long)NW * EMB;
    }

    const int tid = threadIdx.x;
    for (int i = tid; i < NH * HDIM; i += 256) {
        const int r = i >> 6, d = i & 63;
        const size_t gaddr = base + (size_t)r * stride + d;
        QT[QIDX(d, r)] = f2tf(q[gaddr]);
        KT[QIDX(d, r)] = f2tf(k[gaddr]);
        VS[r * ALD + d] = f2tf(v[gaddr]);
    }
    __syncthreads();

    const int warp = tid >> 5, lane = tid & 31;
    const int g8 = lane >> 2, tig = lane & 3;
    const int wm = (warp & 3) * 16;
    const int wn = (warp >> 2) * 32;

    // ---- S = Q K^T ----
    float acc[4][4];
    #pragma unroll
    for (int nt = 0; nt < 4; ++nt)
        #pragma unroll
        for (int l = 0; l < 4; ++l) acc[nt][l] = 0.f;

    #pragma unroll
    for (int kk = 0; kk < 64; kk += 8) {
        unsigned af[4];
        af[0] = QT[QIDX(kk + tig,     wm + g8)];
        af[1] = QT[QIDX(kk + tig,     wm + g8 + 8)];
        af[2] = QT[QIDX(kk + tig + 4, wm + g8)];
        af[3] = QT[QIDX(kk + tig + 4, wm + g8 + 8)];
        #pragma unroll
        for (int nt = 0; nt < 4; ++nt) {
            unsigned bf[2];
            bf[0] = KT[QIDX(kk + tig,     wn + nt * 8 + g8)];
            bf[1] = KT[QIDX(kk + tig + 4, wn + nt * 8 + g8)];
            mma_tf32(acc[nt], af, bf);
        }
    }
    __syncthreads();   // QT/KT reads done before overwriting KT with S

    #pragma unroll
    for (int nt = 0; nt < 4; ++nt) {
        const int c = wn + nt * 8 + tig * 2;
        Sf[(wm + g8    ) * ALD + c]     = acc[nt][0];
        Sf[(wm + g8    ) * ALD + c + 1] = acc[nt][1];
        Sf[(wm + g8 + 8) * ALD + c]     = acc[nt][2];
        Sf[(wm + g8 + 8) * ALD + c + 1] = acc[nt][3];
    }
    __syncthreads();

    // ---- softmax rows -> P^T (tf32) into QT region ----
    for (int x = warp; x < NH; x += 8) {
        const float s0 = Sf[x * ALD + lane];
        const bool hi = (lane < NH - 32);
        const float s1 = hi ? Sf[x * ALD + lane + 32] : -1e30f;
        float m = fmaxf(s0, s1);
        #pragma unroll
        for (int off = 16; off; off >>= 1)
            m = fmaxf(m, __shfl_xor_sync(0xffffffffu, m, off));
        const float e0 = __expf(s0 - m);
        const float e1 = hi ? __expf(s1 - m) : 0.f;
        float sum = e0 + e1;
        #pragma unroll
        for (int off = 16; off; off >>= 1)
            sum += __shfl_xor_sync(0xffffffffu, sum, off);
        const float inv = __fdividef(1.f, sum);

        QT[QIDX(lane, x)] = f2tf(e0 * inv);
        if (hi) QT[QIDX(lane + 32, x)] = f2tf(e1 * inv);
    }
    __syncthreads();

    // ---- O = P V (K=56 -> 7 k8 steps) ----
    float oc[4][4];
    #pragma unroll
    for (int nt = 0; nt < 4; ++nt)
        #pragma unroll
        for (int l = 0; l < 4; ++l) oc[nt][l] = 0.f;

    #pragma unroll
    for (int kk = 0; kk < NH; kk += 8) {
        unsigned af[4];
        af[0] = QT[QIDX(kk + tig,     wm + g8)];
        af[1] = QT[QIDX(kk + tig,     wm + g8 + 8)];
        af[2] = QT[QIDX(kk + tig + 4, wm + g8)];
        af[3] = QT[QIDX(kk + tig + 4, wm + g8 + 8)];
        #pragma unroll
        for (int nt = 0; nt < 4; ++nt) {
            unsigned bf[2];
            bf[0] = VS[(kk + tig    ) * ALD + wn + nt * 8 + g8];
            bf[1] = VS[(kk + tig + 4) * ALD + wn + nt * 8 + g8];
            mma_tf32(oc[nt], af, bf);
        }
    }

    const int r0 = wm + g8, r1 = wm + g8 + 8;
    #pragma unroll
    for (int nt = 0; nt < 4; ++nt) {
        const int c = wn + nt * 8 + tig * 2;
        if (r0 < NH) {
            o[base + (size_t)r0 * stride + c]     = oc[nt][0];
            o[base + (size_t)r0 * stride + c + 1] = oc[nt][1];
        }
        if (r1 < NH) {
            o[base + (size_t)r1 * stride + c]     = oc[nt][2];
            o[base + (size_t)r1 * stride + c + 1] = oc[nt][3];
        }
    }
}

// ---------------- launch ----------------
extern "C" void kernel_launch(void* const* d_in, const int* in_sizes, int n_in,
                              void* d_out, int out_size)
{
    (void)in_sizes; (void)n_in; (void)out_size;
    const float* x  = (const float*)d_in[0];
    const float* Wq = (const float*)d_in[1];
    const float* bq = (const float*)d_in[2];
    const float* Wk = (const float*)d_in[3];
    const float* bk = (const float*)d_in[4];
    const float* Wv = (const float*)d_in[5];
    const float* bv = (const float*)d_in[6];
    const float* Wo = (const float*)d_in[7];
    const float* bo = (const float*)d_in[8];
    float* out = (float*)d_out;

    float *qp, *kp, *vp;
    cudaGetSymbolAddress((void**)&qp, g_q);
    cudaGetSymbolAddress((void**)&kp, g_k);
    cudaGetSymbolAddress((void**)&vp, g_v);

    cudaFuncSetAttribute(gemm_tf32c, cudaFuncAttributeMaxDynamicSharedMemorySize, GEMM_SMEM);
    cudaFuncSetAttribute(attn_tc, cudaFuncAttributeMaxDynamicSharedMemorySize, ATT_SMEM);

    // fused QKV projections (K pre-scaled by 1/sqrt(d)); grid.x = 3 weights x 3 n-tiles
    gemm_tf32c<<<dim3(9, NTOK / BM3), 512, GEMM_SMEM>>>(
        x, Wq, Wk, Wv, bq, bk, bv, qp, kp, vp, 1.0f, SCALING, 1.0f);

    // width attention: vw overwrites V
    attn_tc<<<NB * NH * NHEAD, 256, ATT_SMEM>>>(qp, kp, vp, vp, 0);
    // height attention over vw: output overwrites Q
    attn_tc<<<NB * NW * NHEAD, 256, ATT_SMEM>>>(qp, kp, vp, qp, 1);

    // output projection
    gemm_tf32c<<<dim3(3, NTOK / BM3), 512, GEMM_SMEM>>>(
        qp, Wo, Wo, Wo, bo, bo, bo, out, out, out, 1.0f, 1.0f, 1.0f);
}

// round 14
// speedup vs baseline: 1.4104x; 1.0229x over previous
#include <cuda_runtime.h>
#include <cstdint>
#include <cstddef>

// ---------------- problem constants ----------------
#define EMB   768
#define HDIM  64
#define NHEAD 12
#define NB    16
#define NH    56
#define NW    56
#define NTOK  (NB*NH*NW)          // 50176
#define SCALING 0.125f            // 64^-0.5

// ---------------- scratch (device globals; allocation-free) ----------------
__device__ float g_q[(size_t)NTOK * EMB];
__device__ float g_k[(size_t)NTOK * EMB];
__device__ float g_v[(size_t)NTOK * EMB];

// ---------------- tf32 helpers ----------------
__device__ __forceinline__ unsigned f2tf(float x) {
    unsigned r;
    asm("cvt.rna.tf32.f32 %0, %1;" : "=r"(r) : "f"(x));
    return r;
}

__device__ __forceinline__ void mma_tf32(float* d, const unsigned* a, const unsigned* b) {
    asm volatile(
        "mma.sync.aligned.m16n8k8.row.col.f32.tf32.tf32.f32 "
        "{%0,%1,%2,%3}, {%4,%5,%6,%7}, {%8,%9}, {%0,%1,%2,%3};\n"
        : "+f"(d[0]), "+f"(d[1]), "+f"(d[2]), "+f"(d[3])
        : "r"(a[0]), "r"(a[1]), "r"(a[2]), "r"(a[3]),
          "r"(b[0]), "r"(b[1]));
}

// ---------------- GEMM v4 ----------------
// C[M,768] = (A[M,768] @ W[768,768]^T + bias) * scale.
// 512 threads = 16 warps as 4(M) x 4(N); warp tile 32x64 (mt=2 x nt=8).
// BM=128, BN=256, BK=16, double-buffered.
// smem layout: row-major [row][LDK=40 u32]; within a row:
//   [buf0: k'=0..15][buf1: k'=16..31][8 pad]
// k-permutation inside a chunk: k -> k' = (k>>3)*8 + ((k&3)<<1) + ((k>>2)&1)
//   so the mma operand pair (k, k+4) is ADJACENT -> LDS.64 per fragment pair.
// per-row XOR swizzle on k': s(row) = 2*(((row&3)+2*((row>>2)&1))&3)
//   -> STS conflict-free (verified by full 32-lane enumeration)
//   -> fragment LDS.64 conflict-free per half-warp (2-wavefront minimum)
//   -> s constant per thread for fragment loads => zero per-access ALU.
#define BM4 128
#define BN4 256
#define LDK 40
#define BOFF (128*LDK)                      // B rows start (u32 index)
#define GEMM_SMEM ((128 + 256) * LDK * 4)   // 61440 bytes

__global__ __launch_bounds__(512)
void gemm_tf32d(const float* __restrict__ A,
                const float* __restrict__ W0, const float* __restrict__ W1,
                const float* __restrict__ W2,
                const float* __restrict__ b0, const float* __restrict__ b1,
                const float* __restrict__ b2,
                float* __restrict__ C0, float* __restrict__ C1, float* __restrict__ C2,
                float s0, float s1, float s2)
{
    extern __shared__ unsigned usm[];

    const int sel = blockIdx.x / 3;
    const int n0  = (blockIdx.x % 3) * BN4;
    const int m0  = blockIdx.y * BM4;
    const float* W    = (sel == 0) ? W0 : (sel == 1) ? W1 : W2;
    const float* bias = (sel == 0) ? b0 : (sel == 1) ? b1 : b2;
    float* C          = (sel == 0) ? C0 : (sel == 1) ? C1 : C2;
    const float scale = (sel == 0) ? s0 : (sel == 1) ? s1 : s2;

    const int tid = threadIdx.x;
    // loader mapping
    const int kg = tid & 3;            // which 4-float group of the 16-k chunk
    const int ra = tid >> 2;           // row 0..127
    const int kgl = kg & 1, kgh = kg >> 1;
    const unsigned sra = 2u * (((ra & 3) + 2 * ((ra >> 2) & 1)) & 3);
    const unsigned stA = (unsigned)(ra * LDK + kgl + 8 * kgh);
    unsigned jx[4];
    #pragma unroll
    for (int j = 0; j < 4; ++j) jx[j] = (unsigned)(2 * j) ^ sra;

    // compute mapping
    const int warp = tid >> 5, lane = tid & 31;
    const int g = lane >> 2, tig = lane & 3;
    const int wm = (warp & 3) * 32;    // warp M offset
    const int wn = (warp >> 2) * 64;   // warp N offset
    const unsigned sg = 2u * (((g & 3) + 2 * ((g >> 2) & 1)) & 3);
    const unsigned fA = (unsigned)((wm + g) * LDK) + (((unsigned)(2 * tig)) ^ sg);
    const unsigned fB = BOFF + (unsigned)((wn + g) * LDK) + (((unsigned)(2 * tig)) ^ sg);

    const float* Ap  = A + (size_t)(m0 + ra)       * EMB + kg * 4;
    const float* Bq0 = W + (size_t)(n0 + ra)       * EMB + kg * 4;
    const float* Bq1 = W + (size_t)(n0 + ra + 128) * EMB + kg * 4;

    float acc[2][8][4];
    #pragma unroll
    for (int mt = 0; mt < 2; ++mt)
        #pragma unroll
        for (int nt = 0; nt < 8; ++nt)
            #pragma unroll
            for (int l = 0; l < 4; ++l) acc[mt][nt][l] = 0.f;

    // ---- preload chunk 0 into buf 0 ----
    {
        float4 a0 = *(const float4*)(Ap);
        float4 v0 = *(const float4*)(Bq0);
        float4 v1 = *(const float4*)(Bq1);
        const float* aa  = (const float*)&a0;
        const float* bb0 = (const float*)&v0;
        const float* bb1 = (const float*)&v1;
        #pragma unroll
        for (int j = 0; j < 4; ++j) {
            usm[stA + jx[j]]                     = f2tf(aa[j]);
            usm[BOFF + stA + jx[j]]              = f2tf(bb0[j]);
            usm[BOFF + 128 * LDK + stA + jx[j]]  = f2tf(bb1[j]);
        }
    }
    __syncthreads();

    const int NKC = EMB / 16;   // 48
    for (int t = 0; t < NKC; ++t) {
        const unsigned boff = (unsigned)((t & 1) * 16);

        float4 a0, v0, v1;
        const bool havenext = (t + 1 < NKC);
        if (havenext) {
            const int k0 = (t + 1) * 16;
            a0 = *(const float4*)(Ap + k0);
            v0 = *(const float4*)(Bq0 + k0);
            v1 = *(const float4*)(Bq1 + k0);
        }

        #pragma unroll
        for (int kk8 = 0; kk8 < 2; ++kk8) {
            const unsigned koff = boff + kk8 * 8;
            unsigned af[2][4];
            #pragma unroll
            for (int mt = 0; mt < 2; ++mt) {
                const uint2 lo = *(const uint2*)&usm[fA + mt * (16 * LDK) + koff];
                const uint2 hi = *(const uint2*)&usm[fA + mt * (16 * LDK) + 8 * LDK + koff];
                af[mt][0] = lo.x;  // (r,    k)
                af[mt][1] = hi.x;  // (r+8,  k)
                af[mt][2] = lo.y;  // (r,    k+4)
                af[mt][3] = hi.y;  // (r+8,  k+4)
            }
            unsigned bf[8][2];
            #pragma unroll
            for (int nt = 0; nt < 8; ++nt) {
                const uint2 bv = *(const uint2*)&usm[fB + nt * (8 * LDK) + koff];
                bf[nt][0] = bv.x;
                bf[nt][1] = bv.y;
            }
            #pragma unroll
            for (int mt = 0; mt < 2; ++mt)
                #pragma unroll
                for (int nt = 0; nt < 8; ++nt)
                    mma_tf32(acc[mt][nt], af[mt], bf[nt]);
        }

        if (havenext) {
            const unsigned nboff = (unsigned)(((t + 1) & 1) * 16);
            const float* aa  = (const float*)&a0;
            const float* bb0 = (const float*)&v0;
            const float* bb1 = (const float*)&v1;
            #pragma unroll
            for (int j = 0; j < 4; ++j) {
                usm[stA + nboff + jx[j]]                     = f2tf(aa[j]);
                usm[BOFF + stA + nboff + jx[j]]              = f2tf(bb0[j]);
                usm[BOFF + 128 * LDK + stA + nboff + jx[j]]  = f2tf(bb1[j]);
            }
        }
        __syncthreads();
    }

    // ---- epilogue: C = (acc + bias) * scale ----
    #pragma unroll
    for (int mt = 0; mt < 2; ++mt) {
        const int rbase = m0 + wm + mt * 16 + g;
        #pragma unroll
        for (int nt = 0; nt < 8; ++nt) {
            const int cbase = n0 + wn + nt * 8 + tig * 2;
            const float bv0 = bias[cbase];
            const float bv1 = bias[cbase + 1];
            C[(size_t)rbase * EMB + cbase]           = (acc[mt][nt][0] + bv0) * scale;
            C[(size_t)rbase * EMB + cbase + 1]       = (acc[mt][nt][1] + bv1) * scale;
            C[(size_t)(rbase + 8) * EMB + cbase]     = (acc[mt][nt][2] + bv0) * scale;
            C[(size_t)(rbase + 8) * EMB + cbase + 1] = (acc[mt][nt][3] + bv1) * scale;
        }
    }
}

// ---------------- tensor-core axial attention (unchanged from R13 pass) ----------------
#define ALD 72
#define QIDX(d, r) ((d)*ALD + ((r) ^ (((d) & 12) << 1)))
#define ATT_SMEM (3 * 64 * ALD * 4)   // 55296

__global__ __launch_bounds__(256)
void attn_tc(const float* __restrict__ q, const float* __restrict__ k,
             const float* __restrict__ v, float* __restrict__ o, int axis)
{
    extern __shared__ unsigned asm_[];
    unsigned* QT = asm_;                 // swizzled [d][r]; reused as P^T [y][x]
    unsigned* KT = asm_ + 64 * ALD;      // swizzled [d][r]; reused as S (plain float)
    unsigned* VS = asm_ + 2 * 64 * ALD;  // plain [y][d]
    float* Sf = (float*)KT;

    const int bid = blockIdx.x;
    const int n = bid % NHEAD;
    const int rem = bid / NHEAD;
    const int outer = rem % NH;
    const int b = rem / NH;

    size_t base;
    long stride;
    if (axis == 0) {
        base = ((size_t)(b * NH + outer) * NW) * EMB + (size_t)n * HDIM;
        stride = EMB;
    } else {
        base = ((size_t)b * NH * NW + outer) * EMB + (size_t)n * HDIM;
        stride = (long)NW * EMB;
    }

    const int tid = threadIdx.x;
    for (int i = tid; i < NH * HDIM; i += 256) {
        const int r = i >> 6, d = i & 63;
        const size_t gaddr = base + (size_t)r * stride + d;
        QT[QIDX(d, r)] = f2tf(q[gaddr]);
        KT[QIDX(d, r)] = f2tf(k[gaddr]);
        VS[r * ALD + d] = f2tf(v[gaddr]);
    }
    __syncthreads();

    const int warp = tid >> 5, lane = tid & 31;
    const int g8 = lane >> 2, tig = lane & 3;
    const int wm = (warp & 3) * 16;
    const int wn = (warp >> 2) * 32;

    // ---- S = Q K^T ----
    float acc[4][4];
    #pragma unroll
    for (int nt = 0; nt < 4; ++nt)
        #pragma unroll
        for (int l = 0; l < 4; ++l) acc[nt][l] = 0.f;

    #pragma unroll
    for (int kk = 0; kk < 64; kk += 8) {
        unsigned af[4];
        af[0] = QT[QIDX(kk + tig,     wm + g8)];
        af[1] = QT[QIDX(kk + tig,     wm + g8 + 8)];
        af[2] = QT[QIDX(kk + tig + 4, wm + g8)];
        af[3] = QT[QIDX(kk + tig + 4, wm + g8 + 8)];
        #pragma unroll
        for (int nt = 0; nt < 4; ++nt) {
            unsigned bf[2];
            bf[0] = KT[QIDX(kk + tig,     wn + nt * 8 + g8)];
            bf[1] = KT[QIDX(kk + tig + 4, wn + nt * 8 + g8)];
            mma_tf32(acc[nt], af, bf);
        }
    }
    __syncthreads();   // QT/KT reads done before overwriting KT with S

    #pragma unroll
    for (int nt = 0; nt < 4; ++nt) {
        const int c = wn + nt * 8 + tig * 2;
        Sf[(wm + g8    ) * ALD + c]     = acc[nt][0];
        Sf[(wm + g8    ) * ALD + c + 1] = acc[nt][1];
        Sf[(wm + g8 + 8) * ALD + c]     = acc[nt][2];
        Sf[(wm + g8 + 8) * ALD + c + 1] = acc[nt][3];
    }
    __syncthreads();

    // ---- softmax rows -> P^T (tf32) into QT region ----
    for (int x = warp; x < NH; x += 8) {
        const float s0v = Sf[x * ALD + lane];
        const bool hi = (lane < NH - 32);
        const float s1v = hi ? Sf[x * ALD + lane + 32] : -1e30f;
        float m = fmaxf(s0v, s1v);
        #pragma unroll
        for (int off = 16; off; off >>= 1)
            m = fmaxf(m, __shfl_xor_sync(0xffffffffu, m, off));
        const float e0 = __expf(s0v - m);
        const float e1 = hi ? __expf(s1v - m) : 0.f;
        float sum = e0 + e1;
        #pragma unroll
        for (int off = 16; off; off >>= 1)
            sum += __shfl_xor_sync(0xffffffffu, sum, off);
        const float inv = __fdividef(1.f, sum);

        QT[QIDX(lane, x)] = f2tf(e0 * inv);
        if (hi) QT[QIDX(lane + 32, x)] = f2tf(e1 * inv);
    }
    __syncthreads();

    // ---- O = P V (K=56 -> 7 k8 steps) ----
    float oc[4][4];
    #pragma unroll
    for (int nt = 0; nt < 4; ++nt)
        #pragma unroll
        for (int l = 0; l < 4; ++l) oc[nt][l] = 0.f;

    #pragma unroll
    for (int kk = 0; kk < NH; kk += 8) {
        unsigned af[4];
        af[0] = QT[QIDX(kk + tig,     wm + g8)];
        af[1] = QT[QIDX(kk + tig,     wm + g8 + 8)];
        af[2] = QT[QIDX(kk + tig + 4, wm + g8)];
        af[3] = QT[QIDX(kk + tig + 4, wm + g8 + 8)];
        #pragma unroll
        for (int nt = 0; nt < 4; ++nt) {
            unsigned bf[2];
            bf[0] = VS[(kk + tig    ) * ALD + wn + nt * 8 + g8];
            bf[1] = VS[(kk + tig + 4) * ALD + wn + nt * 8 + g8];
            mma_tf32(oc[nt], af, bf);
        }
    }

    const int r0 = wm + g8, r1 = wm + g8 + 8;
    #pragma unroll
    for (int nt = 0; nt < 4; ++nt) {
        const int c = wn + nt * 8 + tig * 2;
        if (r0 < NH) {
            o[base + (size_t)r0 * stride + c]     = oc[nt][0];
            o[base + (size_t)r0 * stride + c + 1] = oc[nt][1];
        }
        if (r1 < NH) {
            o[base + (size_t)r1 * stride + c]     = oc[nt][2];
            o[base + (size_t)r1 * stride + c + 1] = oc[nt][3];
        }
    }
}

// ---------------- launch ----------------
extern "C" void kernel_launch(void* const* d_in, const int* in_sizes, int n_in,
                              void* d_out, int out_size)
{
    (void)in_sizes; (void)n_in; (void)out_size;
    const float* x  = (const float*)d_in[0];
    const float* Wq = (const float*)d_in[1];
    const float* bq = (const float*)d_in[2];
    const float* Wk = (const float*)d_in[3];
    const float* bk = (const float*)d_in[4];
    const float* Wv = (const float*)d_in[5];
    const float* bv = (const float*)d_in[6];
    const float* Wo = (const float*)d_in[7];
    const float* bo = (const float*)d_in[8];
    float* out = (float*)d_out;

    float *qp, *kp, *vp;
    cudaGetSymbolAddress((void**)&qp, g_q);
    cudaGetSymbolAddress((void**)&kp, g_k);
    cudaGetSymbolAddress((void**)&vp, g_v);

    cudaFuncSetAttribute(gemm_tf32d, cudaFuncAttributeMaxDynamicSharedMemorySize, GEMM_SMEM);
    cudaFuncSetAttribute(attn_tc, cudaFuncAttributeMaxDynamicSharedMemorySize, ATT_SMEM);

    // fused QKV projections (K pre-scaled by 1/sqrt(d)); grid.x = 3 weights x 3 n-tiles
    gemm_tf32d<<<dim3(9, NTOK / BM4), 512, GEMM_SMEM>>>(
        x, Wq, Wk, Wv, bq, bk, bv, qp, kp, vp, 1.0f, SCALING, 1.0f);

    // width attention: vw overwrites V
    attn_tc<<<NB * NH * NHEAD, 256, ATT_SMEM>>>(qp, kp, vp, vp, 0);
    // height attention over vw: output overwrites Q
    attn_tc<<<NB * NW * NHEAD, 256, ATT_SMEM>>>(qp, kp, vp, qp, 1);

    // output projection
    gemm_tf32d<<<dim3(3, NTOK / BM4), 512, GEMM_SMEM>>>(
        qp, Wo, Wo, Wo, bo, bo, bo, out, out, out, 1.0f, 1.0f, 1.0f);
}

// round 15
// speedup vs baseline: 1.5831x; 1.1225x over previous
#include <cuda_runtime.h>
#include <cstdint>
#include <cstddef>

// ---------------- problem constants ----------------
#define EMB   768
#define HDIM  64
#define NHEAD 12
#define NB    16
#define NH    56
#define NW    56
#define NTOK  (NB*NH*NW)          // 50176
#define SCALING 0.125f            // 64^-0.5
#define WSZ   (EMB*EMB)

// ---------------- scratch (device globals; allocation-free) ----------------
__device__ float    g_q[(size_t)NTOK * EMB];
__device__ float    g_k[(size_t)NTOK * EMB];
__device__ float    g_v[(size_t)NTOK * EMB];
__device__ unsigned g_xt[(size_t)NTOK * EMB];   // tf32 operand (x, later attn-out)
__device__ unsigned g_wt[(size_t)4 * WSZ];      // tf32 weights Wq,Wk,Wv,Wo

// ---------------- tf32 helpers ----------------
__device__ __forceinline__ unsigned f2tf(float x) {
    unsigned r;
    asm("cvt.rna.tf32.f32 %0, %1;" : "=r"(r) : "f"(x));
    return r;
}

__device__ __forceinline__ void mma_tf32(float* d, const unsigned* a, const unsigned* b) {
    asm volatile(
        "mma.sync.aligned.m16n8k8.row.col.f32.tf32.tf32.f32 "
        "{%0,%1,%2,%3}, {%4,%5,%6,%7}, {%8,%9}, {%0,%1,%2,%3};\n"
        : "+f"(d[0]), "+f"(d[1]), "+f"(d[2]), "+f"(d[3])
        : "r"(a[0]), "r"(a[1]), "r"(a[2]), "r"(a[3]),
          "r"(b[0]), "r"(b[1]));
}

// ---------------- tf32 pre-convert pass ----------------
__global__ __launch_bounds__(256)
void conv_tf32(const float* __restrict__ in, unsigned* __restrict__ out, int n4)
{
    const int i = blockIdx.x * 256 + threadIdx.x;
    if (i < n4) {
        const float4 v = *(const float4*)(in + (size_t)i * 4);
        uint4 o;
        o.x = f2tf(v.x); o.y = f2tf(v.y); o.z = f2tf(v.z); o.w = f2tf(v.w);
        *(uint4*)(out + (size_t)i * 4) = o;
    }
}

// ---------------- GEMM v5 ----------------
// C[M,768] = (A_tf32[M,768] @ W_tf32[768,768]^T + bias) * scale.
// Operands pre-converted to tf32 (no cvt in loop). 512 threads = 16 warps as
// 4(M) x 4(N); warp tile 32x64 (mt=2 x nt=8). BM=128, BN=256, BK=16,
// double-buffered, t-loop unrolled x2 so all smem offsets are immediates.
// smem layout identical to v4 (k-pair interleave + per-row XOR): LDS.64
// fragment pairs, conflict-free STS.32 / LDS.64.
#define BM4 128
#define BN4 256
#define LDK 40
#define BOFF (128*LDK)
#define GEMM_SMEM ((128 + 256) * LDK * 4)   // 61440 bytes

#define STORE3(OFFc, va, v0, v1) do { \
    usm[stA + (OFFc) + jx[0]] = (va).x; \
    usm[stA + (OFFc) + jx[1]] = (va).y; \
    usm[stA + (OFFc) + jx[2]] = (va).z; \
    usm[stA + (OFFc) + jx[3]] = (va).w; \
    usm[BOFF + stA + (OFFc) + jx[0]] = (v0).x; \
    usm[BOFF + stA + (OFFc) + jx[1]] = (v0).y; \
    usm[BOFF + stA + (OFFc) + jx[2]] = (v0).z; \
    usm[BOFF + stA + (OFFc) + jx[3]] = (v0).w; \
    usm[BOFF + 128*LDK + stA + (OFFc) + jx[0]] = (v1).x; \
    usm[BOFF + 128*LDK + stA + (OFFc) + jx[1]] = (v1).y; \
    usm[BOFF + 128*LDK + stA + (OFFc) + jx[2]] = (v1).z; \
    usm[BOFF + 128*LDK + stA + (OFFc) + jx[3]] = (v1).w; \
} while (0)

#define GEMM_STEP(KOFFc) do { \
    _Pragma("unroll") \
    for (int kk8 = 0; kk8 < 2; ++kk8) { \
        const int koff = (KOFFc) + kk8 * 8; \
        unsigned af[2][4]; \
        _Pragma("unroll") \
        for (int mt = 0; mt < 2; ++mt) { \
            const uint2 lo = *(const uint2*)&usm[fA + mt * (16 * LDK) + koff]; \
            const uint2 hi = *(const uint2*)&usm[fA + mt * (16 * LDK) + 8 * LDK + koff]; \
            af[mt][0] = lo.x; af[mt][1] = hi.x; af[mt][2] = lo.y; af[mt][3] = hi.y; \
        } \
        unsigned bf[8][2]; \
        _Pragma("unroll") \
        for (int nt = 0; nt < 8; ++nt) { \
            const uint2 bv = *(const uint2*)&usm[fB + nt * (8 * LDK) + koff]; \
            bf[nt][0] = bv.x; bf[nt][1] = bv.y; \
        } \
        _Pragma("unroll") \
        for (int mt = 0; mt < 2; ++mt) \
            _Pragma("unroll") \
            for (int nt = 0; nt < 8; ++nt) \
                mma_tf32(acc[mt][nt], af[mt], bf[nt]); \
    } \
} while (0)

__global__ __launch_bounds__(512)
void gemm_tf32e(const unsigned* __restrict__ A,
                const unsigned* __restrict__ W0, const unsigned* __restrict__ W1,
                const unsigned* __restrict__ W2,
                const float* __restrict__ b0, const float* __restrict__ b1,
                const float* __restrict__ b2,
                float* __restrict__ C0, float* __restrict__ C1, float* __restrict__ C2,
                float s0, float s1, float s2)
{
    extern __shared__ unsigned usm[];

    const int sel = blockIdx.x / 3;
    const int n0  = (blockIdx.x % 3) * BN4;
    const int m0  = blockIdx.y * BM4;
    const unsigned* W = (sel == 0) ? W0 : (sel == 1) ? W1 : W2;
    const float* bias = (sel == 0) ? b0 : (sel == 1) ? b1 : b2;
    float* C          = (sel == 0) ? C0 : (sel == 1) ? C1 : C2;
    const float scale = (sel == 0) ? s0 : (sel == 1) ? s1 : s2;

    const int tid = threadIdx.x;
    const int kg = tid & 3;
    const int ra = tid >> 2;
    const int kgl = kg & 1, kgh = kg >> 1;
    const unsigned sra = 2u * (((ra & 3) + 2 * ((ra >> 2) & 1)) & 3);
    const unsigned stA = (unsigned)(ra * LDK + kgl + 8 * kgh);
    unsigned jx[4];
    #pragma unroll
    for (int j = 0; j < 4; ++j) jx[j] = (unsigned)(2 * j) ^ sra;

    const int warp = tid >> 5, lane = tid & 31;
    const int g = lane >> 2, tig = lane & 3;
    const int wm = (warp & 3) * 32;
    const int wn = (warp >> 2) * 64;
    const unsigned sg = 2u * (((g & 3) + 2 * ((g >> 2) & 1)) & 3);
    const unsigned fA = (unsigned)((wm + g) * LDK) + (((unsigned)(2 * tig)) ^ sg);
    const unsigned fB = BOFF + (unsigned)((wn + g) * LDK) + (((unsigned)(2 * tig)) ^ sg);

    const unsigned* Ap  = A + (size_t)(m0 + ra)       * EMB + kg * 4;
    const unsigned* Bp0 = W + (size_t)(n0 + ra)       * EMB + kg * 4;
    const unsigned* Bp1 = W + (size_t)(n0 + ra + 128) * EMB + kg * 4;

    float acc[2][8][4];
    #pragma unroll
    for (int mt = 0; mt < 2; ++mt)
        #pragma unroll
        for (int nt = 0; nt < 8; ++nt)
            #pragma unroll
            for (int l = 0; l < 4; ++l) acc[mt][nt][l] = 0.f;

    // preload chunk 0 -> buf0
    {
        const uint4 a  = *(const uint4*)(Ap);
        const uint4 w0 = *(const uint4*)(Bp0);
        const uint4 w1 = *(const uint4*)(Bp1);
        STORE3(0, a, w0, w1);
    }
    __syncthreads();

    #pragma unroll 1
    for (int t = 0; t < 48; t += 2) {
        // chunk t on buf0; prefetch chunk t+1 -> buf1 (t+1 always < 48)
        const uint4 a1  = *(const uint4*)(Ap + 16);
        const uint4 w10 = *(const uint4*)(Bp0 + 16);
        const uint4 w11 = *(const uint4*)(Bp1 + 16);
        GEMM_STEP(0);
        STORE3(16, a1, w10, w11);
        __syncthreads();

        // chunk t+1 on buf1; prefetch chunk t+2 -> buf0
        const bool more = (t + 2 < 48);
        uint4 a2, w20, w21;
        if (more) {
            a2  = *(const uint4*)(Ap + 32);
            w20 = *(const uint4*)(Bp0 + 32);
            w21 = *(const uint4*)(Bp1 + 32);
        }
        GEMM_STEP(16);
        if (more) STORE3(0, a2, w20, w21);
        Ap += 32; Bp0 += 32; Bp1 += 32;
        __syncthreads();
    }

    // ---- epilogue: C = (acc + bias) * scale ----
    #pragma unroll
    for (int mt = 0; mt < 2; ++mt) {
        const int rbase = m0 + wm + mt * 16 + g;
        #pragma unroll
        for (int nt = 0; nt < 8; ++nt) {
            const int cbase = n0 + wn + nt * 8 + tig * 2;
            const float bv0 = bias[cbase];
            const float bv1 = bias[cbase + 1];
            C[(size_t)rbase * EMB + cbase]           = (acc[mt][nt][0] + bv0) * scale;
            C[(size_t)rbase * EMB + cbase + 1]       = (acc[mt][nt][1] + bv1) * scale;
            C[(size_t)(rbase + 8) * EMB + cbase]     = (acc[mt][nt][2] + bv0) * scale;
            C[(size_t)(rbase + 8) * EMB + cbase + 1] = (acc[mt][nt][3] + bv1) * scale;
        }
    }
}

// ---------------- tensor-core axial attention v2 ----------------
// 2 heads per CTA; 8 warps = 2 heads x (2m x 2n), warp tile 32x32.
// Per-head smem block (u32): QT[64][72] swizzled (-> P^T), KT[64][72]
// swizzled (-> S float), VS[64][72] plain. Same QIDX swizzle as R13
// (conflict-free fragment LDS; per-element arithmetic order identical).
#define ALD 72
#define QIDX(d, r) ((d)*ALD + ((r) ^ (((d) & 12) << 1)))
#define AH (3 * 64 * ALD)                 // per-head u32 block
#define ATT_SMEM (2 * AH * 4)             // 110592 bytes

__global__ __launch_bounds__(256)
void attn_tc2(const float* __restrict__ q, const float* __restrict__ k,
              const float* __restrict__ v, float* __restrict__ o, int axis)
{
    extern __shared__ unsigned asm_[];

    const int bid = blockIdx.x;
    const int n2 = bid % 6;               // head pair: heads 2*n2, 2*n2+1
    const int rem = bid / 6;
    const int outer = rem % NH;
    const int b = rem / NH;

    size_t tbase;
    long stride;
    if (axis == 0) {
        tbase = ((size_t)(b * NH + outer) * NW) * EMB;
        stride = EMB;
    } else {
        tbase = ((size_t)b * NH * NW + outer) * EMB;
        stride = (long)NW * EMB;
    }
    const size_t base0 = tbase + (size_t)(2 * n2) * HDIM;

    const int tid = threadIdx.x;
    #pragma unroll
    for (int hh = 0; hh < 2; ++hh) {
        unsigned* QTh = asm_ + hh * AH;
        unsigned* KTh = QTh + 64 * ALD;
        unsigned* VSh = KTh + 64 * ALD;
        const size_t hb = base0 + (size_t)hh * HDIM;
        for (int i = tid; i < NH * HDIM; i += 256) {
            const int r = i >> 6, d = i & 63;
            const size_t gaddr = hb + (size_t)r * stride + d;
            QTh[QIDX(d, r)] = f2tf(q[gaddr]);
            KTh[QIDX(d, r)] = f2tf(k[gaddr]);
            VSh[r * ALD + d] = f2tf(v[gaddr]);
        }
    }
    __syncthreads();

    const int warp = tid >> 5, lane = tid & 31;
    const int g8 = lane >> 2, tig = lane & 3;
    const int h = warp >> 2;              // head within CTA
    const int w4 = warp & 3;
    const int wm = (w4 & 1) * 32;         // 2 m-halves
    const int wn = (w4 >> 1) * 32;        // 2 n-halves

    unsigned* QT = asm_ + h * AH;
    unsigned* KT = QT + 64 * ALD;
    unsigned* VS = KT + 64 * ALD;
    float* Sf = (float*)KT;

    // ---- S = Q K^T (64x64x64, warp does 32x32) ----
    float acc[2][4][4];
    #pragma unroll
    for (int mt = 0; mt < 2; ++mt)
        #pragma unroll
        for (int nt = 0; nt < 4; ++nt)
            #pragma unroll
            for (int l = 0; l < 4; ++l) acc[mt][nt][l] = 0.f;

    #pragma unroll
    for (int kk = 0; kk < 64; kk += 8) {
        unsigned af[2][4];
        #pragma unroll
        for (int mt = 0; mt < 2; ++mt) {
            const int r = wm + mt * 16 + g8;
            af[mt][0] = QT[QIDX(kk + tig,     r)];
            af[mt][1] = QT[QIDX(kk + tig,     r + 8)];
            af[mt][2] = QT[QIDX(kk + tig + 4, r)];
            af[mt][3] = QT[QIDX(kk + tig + 4, r + 8)];
        }
        #pragma unroll
        for (int nt = 0; nt < 4; ++nt) {
            unsigned bf[2];
            const int c = wn + nt * 8 + g8;
            bf[0] = KT[QIDX(kk + tig,     c)];
            bf[1] = KT[QIDX(kk + tig + 4, c)];
            #pragma unroll
            for (int mt = 0; mt < 2; ++mt)
                mma_tf32(acc[mt][nt], af[mt], bf);
        }
    }
    __syncthreads();   // QT/KT reads done before overwriting KT with S

    #pragma unroll
    for (int mt = 0; mt < 2; ++mt) {
        const int r = wm + mt * 16 + g8;
        #pragma unroll
        for (int nt = 0; nt < 4; ++nt) {
            const int c = wn + nt * 8 + tig * 2;
            Sf[r * ALD + c]           = acc[mt][nt][0];
            Sf[r * ALD + c + 1]       = acc[mt][nt][1];
            Sf[(r + 8) * ALD + c]     = acc[mt][nt][2];
            Sf[(r + 8) * ALD + c + 1] = acc[mt][nt][3];
        }
    }
    __syncthreads();

    // ---- softmax rows -> P^T (tf32) into QT region (per head, 4 warps) ----
    for (int x = w4; x < NH; x += 4) {
        const float s0v = Sf[x * ALD + lane];
        const bool hi = (lane < NH - 32);
        const float s1v = hi ? Sf[x * ALD + lane + 32] : -1e30f;
        float m = fmaxf(s0v, s1v);
        #pragma unroll
        for (int off = 16; off; off >>= 1)
            m = fmaxf(m, __shfl_xor_sync(0xffffffffu, m, off));
        const float e0 = __expf(s0v - m);
        const float e1 = hi ? __expf(s1v - m) : 0.f;
        float sum = e0 + e1;
        #pragma unroll
        for (int off = 16; off; off >>= 1)
            sum += __shfl_xor_sync(0xffffffffu, sum, off);
        const float inv = __fdividef(1.f, sum);

        QT[QIDX(lane, x)] = f2tf(e0 * inv);
        if (hi) QT[QIDX(lane + 32, x)] = f2tf(e1 * inv);
    }
    __syncthreads();

    // ---- O = P V (K=56 -> 7 k8 steps) ----
    float oc[2][4][4];
    #pragma unroll
    for (int mt = 0; mt < 2; ++mt)
        #pragma unroll
        for (int nt = 0; nt < 4; ++nt)
            #pragma unroll
            for (int l = 0; l < 4; ++l) oc[mt][nt][l] = 0.f;

    #pragma unroll
    for (int kk = 0; kk < NH; kk += 8) {
        unsigned af[2][4];
        #pragma unroll
        for (int mt = 0; mt < 2; ++mt) {
            const int r = wm + mt * 16 + g8;
            af[mt][0] = QT[QIDX(kk + tig,     r)];
            af[mt][1] = QT[QIDX(kk + tig,     r + 8)];
            af[mt][2] = QT[QIDX(kk + tig + 4, r)];
            af[mt][3] = QT[QIDX(kk + tig + 4, r + 8)];
        }
        #pragma unroll
        for (int nt = 0; nt < 4; ++nt) {
            unsigned bf[2];
            const int c = wn + nt * 8 + g8;
            bf[0] = VS[(kk + tig    ) * ALD + c];
            bf[1] = VS[(kk + tig + 4) * ALD + c];
            #pragma unroll
            for (int mt = 0; mt < 2; ++mt)
                mma_tf32(oc[mt][nt], af[mt], bf);
        }
    }

    const size_t obase = base0 + (size_t)h * HDIM;
    #pragma unroll
    for (int mt = 0; mt < 2; ++mt) {
        const int r0 = wm + mt * 16 + g8, r1 = r0 + 8;
        #pragma unroll
        for (int nt = 0; nt < 4; ++nt) {
            const int c = wn + nt * 8 + tig * 2;
            if (r0 < NH) {
                o[obase + (size_t)r0 * stride + c]     = oc[mt][nt][0];
                o[obase + (size_t)r0 * stride + c + 1] = oc[mt][nt][1];
            }
            if (r1 < NH) {
                o[obase + (size_t)r1 * stride + c]     = oc[mt][nt][2];
                o[obase + (size_t)r1 * stride + c + 1] = oc[mt][nt][3];
            }
        }
    }
}

// ---------------- launch ----------------
extern "C" void kernel_launch(void* const* d_in, const int* in_sizes, int n_in,
                              void* d_out, int out_size)
{
    (void)in_sizes; (void)n_in; (void)out_size;
    const float* x  = (const float*)d_in[0];
    const float* Wq = (const float*)d_in[1];
    const float* bq = (const float*)d_in[2];
    const float* Wk = (const float*)d_in[3];
    const float* bk = (const float*)d_in[4];
    const float* Wv = (const float*)d_in[5];
    const float* bv = (const float*)d_in[6];
    const float* Wo = (const float*)d_in[7];
    const float* bo = (const float*)d_in[8];
    float* out = (float*)d_out;

    float *qp, *kp, *vp;
    unsigned *xt, *wt;
    cudaGetSymbolAddress((void**)&qp, g_q);
    cudaGetSymbolAddress((void**)&kp, g_k);
    cudaGetSymbolAddress((void**)&vp, g_v);
    cudaGetSymbolAddress((void**)&xt, g_xt);
    cudaGetSymbolAddress((void**)&wt, g_wt);

    cudaFuncSetAttribute(gemm_tf32e, cudaFuncAttributeMaxDynamicSharedMemorySize, GEMM_SMEM);
    cudaFuncSetAttribute(attn_tc2, cudaFuncAttributeMaxDynamicSharedMemorySize, ATT_SMEM);

    const int nx4 = NTOK * EMB / 4;
    const int nw4 = WSZ / 4;

    // pre-convert operands to tf32 (once)
    conv_tf32<<<(nx4 + 255) / 256, 256>>>(x, xt, nx4);
    conv_tf32<<<(nw4 + 255) / 256, 256>>>(Wq, wt + 0 * WSZ, nw4);
    conv_tf32<<<(nw4 + 255) / 256, 256>>>(Wk, wt + 1 * WSZ, nw4);
    conv_tf32<<<(nw4 + 255) / 256, 256>>>(Wv, wt + 2 * WSZ, nw4);
    conv_tf32<<<(nw4 + 255) / 256, 256>>>(Wo, wt + 3 * WSZ, nw4);

    // fused QKV projections (K pre-scaled by 1/sqrt(d))
    gemm_tf32e<<<dim3(9, NTOK / BM4), 512, GEMM_SMEM>>>(
        xt, wt, wt + WSZ, wt + 2 * WSZ, bq, bk, bv, qp, kp, vp, 1.0f, SCALING, 1.0f);

    // width attention: vw overwrites V ; height attention: overwrites Q
    attn_tc2<<<NB * NH * 6, 256, ATT_SMEM>>>(qp, kp, vp, vp, 0);
    attn_tc2<<<NB * NW * 6, 256, ATT_SMEM>>>(qp, kp, vp, qp, 1);

    // convert attention output, then output projection
    conv_tf32<<<(nx4 + 255) / 256, 256>>>(qp, xt, nx4);
    gemm_tf32e<<<dim3(3, NTOK / BM4), 512, GEMM_SMEM>>>(
        xt, wt + 3 * WSZ, wt + 3 * WSZ, wt + 3 * WSZ, bo, bo, bo,
        out, out, out, 1.0f, 1.0f, 1.0f);
}